// round 1
// baseline (speedup 1.0000x reference)
#include <cuda_runtime.h>
#include <math.h>

#define Bn 16
#define Cc 96
#define HW 16384
#define NPIX (Bn*Cc*HW)      // 25,165,824
#define GN_N 393216          // 24*16384 elements per (b,group)

// ---------------- scratch (device globals: no allocation allowed) ----------
__device__ float g_buf1[NPIX];          // conv1 out, later conv2 out
__device__ float g_buf2[NPIX];          // residual R (post FiLM)
__device__ float g_buf3[NPIX];          // attention output A
__device__ float g_partials[3*64*8*2];  // per-(b,g) partial sums
__device__ float g_stats[3*64*2];       // (mean, rstd) per (b,g)
__device__ float g_film[Bn*192];        // silu(t_emb@wt.T+bt)

// ---------------- conv3x3 (implicit GEMM, row-tile) ------------------------
// grid (128 rows, 3 co-groups, 16 batch), 256 threads
// block computes out[b, co0:co0+32, h, 0:128]; thread tile 4co x 4w
__global__ __launch_bounds__(256) void conv3x3_k(
    const float* __restrict__ in, const float* __restrict__ w,
    const float* __restrict__ bias, float* __restrict__ out)
{
    __shared__ float sIn[8][3][132];   // ci, ky, col (col = gw+1), padded to 132
    __shared__ float sW[8][9][32];     // ci, ky*3+kx, co_local

    int h   = blockIdx.x;
    int co0 = blockIdx.y * 32;
    int b   = blockIdx.z;
    int tid = threadIdx.x;
    int tc  = tid >> 5;    // 0..7 -> co_local = tc*4
    int tw  = tid & 31;    // w0 = tw*4

    float acc[4][4];
#pragma unroll
    for (int i = 0; i < 4; i++)
#pragma unroll
        for (int j = 0; j < 4; j++) acc[i][j] = 0.f;

    for (int cc = 0; cc < Cc; cc += 8) {
        // stage input rows h-1..h+1, cols -1..128 for 8 input channels
        for (int i = tid; i < 8*3*130; i += 256) {
            int col = i % 130; int t = i / 130;
            int ky = t % 3;    int ci = t / 3;
            int gh = h + ky - 1, gw = col - 1;
            float v = 0.f;
            if ((unsigned)gh < 128u && (unsigned)gw < 128u)
                v = in[(((size_t)(b*Cc + cc + ci)) << 14) + (gh << 7) + gw];
            sIn[ci][ky][col] = v;
        }
        // stage weights: w[co][ci][ky][kx] -> sW[ci][kk][co_local]
        for (int i = tid; i < 8*9*32; i += 256) {
            int col = i & 31; int t = i >> 5;
            int kk = t % 9;   int ci = t / 9;
            sW[ci][kk][col] = w[((co0 + col)*Cc + cc + ci)*9 + kk];
        }
        __syncthreads();

#pragma unroll 2
        for (int ci = 0; ci < 8; ci++) {
#pragma unroll
            for (int ky = 0; ky < 3; ky++) {
                float4 b0 = *(const float4*)&sIn[ci][ky][tw*4];
                float4 b1 = *(const float4*)&sIn[ci][ky][tw*4 + 4];
                float bv[8] = {b0.x,b0.y,b0.z,b0.w,b1.x,b1.y,b1.z,b1.w};
#pragma unroll
                for (int kx = 0; kx < 3; kx++) {
                    float4 a = *(const float4*)&sW[ci][ky*3+kx][tc*4];
                    float av[4] = {a.x,a.y,a.z,a.w};
#pragma unroll
                    for (int c = 0; c < 4; c++)
#pragma unroll
                        for (int j = 0; j < 4; j++)
                            acc[c][j] += av[c]*bv[j+kx];
                }
            }
        }
        __syncthreads();
    }
#pragma unroll
    for (int c = 0; c < 4; c++) {
        float bs = bias[co0 + tc*4 + c];
        float4 o = {acc[c][0]+bs, acc[c][1]+bs, acc[c][2]+bs, acc[c][3]+bs};
        *(float4*)&out[(((size_t)(b*Cc + co0 + tc*4 + c)) << 14) + (h << 7) + tw*4] = o;
    }
}

// ---------------- GroupNorm reduce (deterministic, 2-stage) -----------------
// grid (64 bg, 8 chunks), 256 threads; writes partials[bg][chunk] = (sum,sumsq)
__global__ __launch_bounds__(256) void gn_reduce_k(
    const float* __restrict__ x, float* __restrict__ partials)
{
    int bg = blockIdx.x, chunk = blockIdx.y;
    const float4* p = (const float4*)(x + (size_t)bg*GN_N + (size_t)chunk*49152);
    float sx=0,sy=0,sz=0,sw=0, qx=0,qy=0,qz=0,qw=0;
    for (int i = threadIdx.x; i < 12288; i += 256) {
        float4 v = p[i];
        sx += v.x; sy += v.y; sz += v.z; sw += v.w;
        qx += v.x*v.x; qy += v.y*v.y; qz += v.z*v.z; qw += v.w*v.w;
    }
    __shared__ double sh[512];
    int tid = threadIdx.x;
    sh[tid]       = (double)sx + sy + sz + sw;
    sh[256 + tid] = (double)qx + qy + qz + qw;
    __syncthreads();
    for (int st = 128; st > 0; st >>= 1) {
        if (tid < st) { sh[tid] += sh[tid+st]; sh[256+tid] += sh[256+tid+st]; }
        __syncthreads();
    }
    if (tid == 0) {
        partials[(bg*8 + chunk)*2 + 0] = (float)sh[0];
        partials[(bg*8 + chunk)*2 + 1] = (float)sh[256];
    }
}

__global__ void gn_finalize_k(const float* __restrict__ partials,
                              float* __restrict__ stats)
{
    int bg = threadIdx.x;  // 64 threads
    float s = 0, q = 0;
    for (int c = 0; c < 8; c++) {
        s += partials[(bg*8 + c)*2 + 0];
        q += partials[(bg*8 + c)*2 + 1];
    }
    float mean = s * (1.f/393216.f);
    float var  = q * (1.f/393216.f) - mean*mean;
    stats[bg*2 + 0] = mean;
    stats[bg*2 + 1] = rsqrtf(var + 1e-5f);
}

// ---------------- time-embedding MLP ---------------------------------------
// grid 16, 192 threads: film[b][j] = silu(t_emb[b] . wt[j] + bt[j])
__global__ void temb_k(const float* __restrict__ te, const float* __restrict__ wt,
                       const float* __restrict__ bt, float* __restrict__ film)
{
    __shared__ float sh[256];
    int b = blockIdx.x, j = threadIdx.x;
    for (int i = threadIdx.x; i < 256; i += 192) sh[i] = te[b*256 + i];
    __syncthreads();
    const float* wr = wt + j*256;
    float s = bt[j];
#pragma unroll 4
    for (int k = 0; k < 256; k++) s += sh[k]*wr[k];
    s = s / (1.f + expf(-s));
    film[b*192 + j] = s;
}

// ---------------- apply GN1 + SiLU + FiLM  (buf1 -> R) ----------------------
__global__ __launch_bounds__(256) void apply1_k(
    const float* __restrict__ x, const float* __restrict__ stats,
    const float* __restrict__ g1, const float* __restrict__ be1,
    const float* __restrict__ film, float* __restrict__ out)
{
    int idx4 = blockIdx.x*256 + threadIdx.x;
    if (idx4 >= NPIX/4) return;
    int flat = idx4 << 2;
    int cimg = flat >> 14;
    int b = cimg / 96, c = cimg - 96*b;
    int bg = b*4 + c/24;
    float mean = stats[bg*2], rstd = stats[bg*2+1];
    float gam = g1[c]*rstd;
    float bet = be1[c] - mean*gam;
    float shf = 1.f + film[b*192 + c];
    float bia = film[b*192 + 96 + c];
    float4 v = *(const float4*)&x[flat];
    float t;
    t = v.x*gam + bet; t = t/(1.f+expf(-t)); v.x = t*shf + bia;
    t = v.y*gam + bet; t = t/(1.f+expf(-t)); v.y = t*shf + bia;
    t = v.z*gam + bet; t = t/(1.f+expf(-t)); v.z = t*shf + bia;
    t = v.w*gam + bet; t = t/(1.f+expf(-t)); v.w = t*shf + bia;
    *(float4*)&out[flat] = v;
}

// ---------------- final apply: SiLU(GN(conv2)) -> d_out ---------------------
__global__ __launch_bounds__(256) void apply3_k(
    const float* __restrict__ x, const float* __restrict__ stats,
    const float* __restrict__ g2, const float* __restrict__ be2,
    float* __restrict__ out)
{
    int idx4 = blockIdx.x*256 + threadIdx.x;
    if (idx4 >= NPIX/4) return;
    int flat = idx4 << 2;
    int cimg = flat >> 14;
    int b = cimg / 96, c = cimg - 96*b;
    int bg = b*4 + c/24;
    float mean = stats[bg*2], rstd = stats[bg*2+1];
    float gam = g2[c]*rstd;
    float bet = be2[c] - mean*gam;
    float4 v = *(const float4*)&x[flat];
    float t;
    t = v.x*gam + bet; v.x = t/(1.f+expf(-t));
    t = v.y*gam + bet; v.y = t/(1.f+expf(-t));
    t = v.z*gam + bet; v.z = t/(1.f+expf(-t));
    t = v.w*gam + bet; v.w = t/(1.f+expf(-t));
    *(float4*)&out[flat] = v;
}

// ---------------- fused window attention ------------------------------------
// grid (256 windows, 16 batch), 256 threads, dynamic smem.
// GN2 applied on load from R; qkv 1x1 + 6x6 channel-attention + proj 1x1;
// branch0: A = R + 0.5*y ; branch1 (shift=4): A += 0.5*y.
__global__ __launch_bounds__(256) void win_attn_k(
    const float* __restrict__ R, const float* __restrict__ stats,
    const float* __restrict__ ga, const float* __restrict__ ba,
    const float* __restrict__ qkv_w, const float* __restrict__ qkv_b,
    const float* __restrict__ proj_w, const float* __restrict__ proj_b,
    float* __restrict__ A, int shift, int accumulate)
{
    extern __shared__ float sm[];
    float* xw    = sm;              // [96][64]
    float* sqkv  = xw + 6144;       // [18][64]
    float* sout  = sqkv + 1152;     // [96][64]
    float* sattn = sout + 6144;     // [36]+pad

    int b   = blockIdx.y;
    int hn  = blockIdx.x >> 4, wn = blockIdx.x & 15;
    int tid = threadIdx.x;
    int h0  = hn*8 + shift, w0 = wn*8 + shift;

    // load window with GN2 applied
    for (int i = tid; i < 6144; i += 256) {
        int c = i >> 6, l = i & 63;
        int gh = (h0 + (l >> 3)) & 127;
        int gw = (w0 + (l & 7))  & 127;
        float v = R[(((size_t)(b*96 + c)) << 14) + (gh << 7) + gw];
        int bg = b*4 + c/24;
        xw[i] = (v - stats[bg*2]) * stats[bg*2+1] * ga[c] + ba[c];
    }
    __syncthreads();

    const float scale = 0.4082482904638630f;  // 6^-0.5
    for (int head = 0; head < 16; head++) {
        // qkv for this head: 18 rows x 64 cols (as 16 float4 quads)
        for (int i = tid; i < 288; i += 256) {
            int rr = i >> 4, lq = i & 15;
            int s = rr / 6, d = rr - 6*s;
            int grow = s*96 + head*6 + d;
            const float* wr = qkv_w + grow*96;
            float ax=0, ay=0, az=0, aw=0;
#pragma unroll 4
            for (int c = 0; c < 96; c++) {
                float wv = wr[c];
                float4 xv = *(const float4*)&xw[(c << 6) + (lq << 2)];
                ax += wv*xv.x; ay += wv*xv.y; az += wv*xv.z; aw += wv*xv.w;
            }
            float bb = qkv_b[grow];
            float4 o = {ax+bb, ay+bb, az+bb, aw+bb};
            *(float4*)&sqkv[(rr << 6) + (lq << 2)] = o;
        }
        __syncthreads();

        // attn[d][e] = scale * sum_l q[d,l]*k[e,l]
        if (tid < 36) {
            int d = tid / 6, e = tid - 6*(tid/6);
            float acc = 0;
#pragma unroll 8
            for (int l = 0; l < 64; l++)
                acc += sqkv[(d << 6) + l] * sqkv[((6+e) << 6) + l];
            sattn[tid] = acc * scale;
        }
        __syncthreads();

        // softmax over e (row-wise)
        if (tid < 6) {
            float m = -1e30f;
#pragma unroll
            for (int e = 0; e < 6; e++) m = fmaxf(m, sattn[tid*6 + e]);
            float ss = 0;
#pragma unroll
            for (int e = 0; e < 6; e++) {
                float ex = expf(sattn[tid*6 + e] - m);
                sattn[tid*6 + e] = ex; ss += ex;
            }
            float inv = 1.f/ss;
#pragma unroll
            for (int e = 0; e < 6; e++) sattn[tid*6 + e] *= inv;
        }
        __syncthreads();

        // out[d][l] = sum_e attn[d][e]*v[e][l]
        if (tid < 96) {
            int d = tid >> 4, lq = tid & 15;
            float ax=0, ay=0, az=0, aw=0;
#pragma unroll
            for (int e = 0; e < 6; e++) {
                float a = sattn[d*6 + e];
                float4 vv = *(const float4*)&sqkv[((12+e) << 6) + (lq << 2)];
                ax += a*vv.x; ay += a*vv.y; az += a*vv.z; aw += a*vv.w;
            }
            float4 o = {ax, ay, az, aw};
            *(float4*)&sout[((head*6 + d) << 6) + (lq << 2)] = o;
        }
        __syncthreads();
    }

    // proj + residual/average + store
    for (int i = tid; i < 1536; i += 256) {
        int co = i >> 4, lq = i & 15;
        const float* wr = proj_w + co*96;
        float ax=0, ay=0, az=0, aw=0;
#pragma unroll 4
        for (int c = 0; c < 96; c++) {
            float wv = wr[c];
            float4 xv = *(const float4*)&sout[(c << 6) + (lq << 2)];
            ax += wv*xv.x; ay += wv*xv.y; az += wv*xv.z; aw += wv*xv.w;
        }
        float bb = proj_b[co];
        int l = lq << 2;
        int gh = (h0 + (l >> 3)) & 127;
        int gw = (w0 + (l & 7))  & 127;
        size_t oidx = (((size_t)(b*96 + co)) << 14) + (gh << 7) + gw;
        float4 y = {0.5f*(ax+bb), 0.5f*(ay+bb), 0.5f*(az+bb), 0.5f*(aw+bb)};
        float4 cur;
        if (accumulate) cur = *(const float4*)&A[oidx];
        else            cur = *(const float4*)&R[oidx];
        cur.x += y.x; cur.y += y.y; cur.z += y.z; cur.w += y.w;
        *(float4*)&A[oidx] = cur;
    }
}

// ---------------- launch ----------------------------------------------------
extern "C" void kernel_launch(void* const* d_in, const int* in_sizes, int n_in,
                              void* d_out, int out_size)
{
    const float* x      = (const float*)d_in[0];
    const float* t_emb  = (const float*)d_in[1];
    const float* w1     = (const float*)d_in[2];
    const float* b1     = (const float*)d_in[3];
    const float* g1     = (const float*)d_in[4];
    const float* be1    = (const float*)d_in[5];
    const float* wt     = (const float*)d_in[6];
    const float* bt     = (const float*)d_in[7];
    const float* qkv_w  = (const float*)d_in[8];
    const float* qkv_b  = (const float*)d_in[9];
    const float* proj_w = (const float*)d_in[10];
    const float* proj_b = (const float*)d_in[11];
    const float* ga     = (const float*)d_in[12];
    const float* ba     = (const float*)d_in[13];
    const float* w2     = (const float*)d_in[14];
    const float* b2     = (const float*)d_in[15];
    const float* g2     = (const float*)d_in[16];
    const float* be2    = (const float*)d_in[17];
    float* out = (float*)d_out;

    float *buf1, *buf2, *buf3, *partials, *stats, *film;
    cudaGetSymbolAddress((void**)&buf1, g_buf1);
    cudaGetSymbolAddress((void**)&buf2, g_buf2);
    cudaGetSymbolAddress((void**)&buf3, g_buf3);
    cudaGetSymbolAddress((void**)&partials, g_partials);
    cudaGetSymbolAddress((void**)&stats, g_stats);
    cudaGetSymbolAddress((void**)&film, g_film);

    const int ATTN_SMEM = (6144 + 1152 + 6144 + 64) * 4;  // 54,016 B
    cudaFuncSetAttribute(win_attn_k, cudaFuncAttributeMaxDynamicSharedMemorySize,
                         ATTN_SMEM);

    dim3 cgrid(128, 3, 16);
    dim3 rgrid(64, 8);

    // 1. conv1: x -> buf1
    conv3x3_k<<<cgrid, 256>>>(x, w1, b1, buf1);
    // 2. GN1 stats
    gn_reduce_k<<<rgrid, 256>>>(buf1, partials + 0*64*8*2);
    gn_finalize_k<<<1, 64>>>(partials + 0*64*8*2, stats + 0*64*2);
    // 3. time embedding
    temb_k<<<16, 192>>>(t_emb, wt, bt, film);
    // 4. R = FiLM(SiLU(GN1(buf1)))
    apply1_k<<<NPIX/4/256, 256>>>(buf1, stats + 0*64*2, g1, be1, film, buf2);
    // 5. GN2 stats (over R)
    gn_reduce_k<<<rgrid, 256>>>(buf2, partials + 1*64*8*2);
    gn_finalize_k<<<1, 64>>>(partials + 1*64*8*2, stats + 1*64*2);
    // 6/7. windowed attention, both branches; A = R + 0.5*(y0 + y1)
    win_attn_k<<<dim3(256,16), 256, ATTN_SMEM>>>(buf2, stats + 1*64*2, ga, ba,
        qkv_w, qkv_b, proj_w, proj_b, buf3, 0, 0);
    win_attn_k<<<dim3(256,16), 256, ATTN_SMEM>>>(buf2, stats + 1*64*2, ga, ba,
        qkv_w, qkv_b, proj_w, proj_b, buf3, 4, 1);
    // 8. conv2: A -> buf1
    conv3x3_k<<<cgrid, 256>>>(buf3, w2, b2, buf1);
    // 9. GN3 stats
    gn_reduce_k<<<rgrid, 256>>>(buf1, partials + 2*64*8*2);
    gn_finalize_k<<<1, 64>>>(partials + 2*64*8*2, stats + 2*64*2);
    // 10. out = SiLU(GN3(buf1))
    apply3_k<<<NPIX/4/256, 256>>>(buf1, stats + 2*64*2, g2, be2, out);
}

// round 2
// speedup vs baseline: 1.6293x; 1.6293x over previous
#include <cuda_runtime.h>
#include <math.h>

#define Bn 16
#define Cc 96
#define NPIX (16*96*16384)      // 25,165,824
#define GN_N 393216

// ---------------- scratch (device globals) ----------------------------------
__device__ float g_buf1[NPIX];          // conv out / attn-branch0 out
__device__ float g_buf2[NPIX];          // residual R
__device__ float g_buf3[NPIX];          // attention block output A
__device__ float g_buf4[NPIX];          // attn-branch1 out
__device__ float g_qkv[3*NPIX];         // qkv tensor (288 ch)
__device__ float g_partials[3*64*8*2];
__device__ float g_stats[3*64*2];
__device__ float g_film[16*192];

// ---------------- conv3x3: block 32co x 128w (one row), thread 8co x 4w -----
__global__ __launch_bounds__(128) void conv3x3_k(
    const float* __restrict__ in, const float* __restrict__ w,
    const float* __restrict__ bias, float* __restrict__ out)
{
    __shared__ float sIn[8][3][132];
    __shared__ float sW[8][9][32];

    int h = blockIdx.x, co0 = blockIdx.y*32, b = blockIdx.z;
    int tid = threadIdx.x;
    int tc = tid >> 5;          // 0..3 -> co_local = tc*8
    int tw = tid & 31;          // w0 = tw*4
    int w0 = tw*4;

    float acc[8][4];
#pragma unroll
    for (int c = 0; c < 8; c++)
#pragma unroll
        for (int j = 0; j < 4; j++) acc[c][j] = 0.f;

    for (int cc = 0; cc < 96; cc += 8) {
        for (int i = tid; i < 8*3*130; i += 128) {
            int col = i % 130; int t = i / 130;
            int ky = t % 3, ci = t / 3;
            int gh = h + ky - 1, gw = col - 1;
            float v = 0.f;
            if ((unsigned)gh < 128u && (unsigned)gw < 128u)
                v = in[(((size_t)(b*96 + cc + ci)) << 14) + (gh << 7) + gw];
            sIn[ci][ky][col] = v;
        }
        for (int i = tid; i < 8*9*32; i += 128) {
            int col = i & 31; int t = i >> 5;
            int kk = t % 9, ci = t / 9;
            sW[ci][kk][col] = w[((co0 + col)*96 + cc + ci)*9 + kk];
        }
        __syncthreads();

#pragma unroll
        for (int ci = 0; ci < 8; ci++) {
#pragma unroll
            for (int ky = 0; ky < 3; ky++) {
                float4 p0 = *(const float4*)&sIn[ci][ky][w0];
                float2 p1 = *(const float2*)&sIn[ci][ky][w0 + 4];
                float bv[6] = {p0.x, p0.y, p0.z, p0.w, p1.x, p1.y};
#pragma unroll
                for (int kx = 0; kx < 3; kx++) {
                    float4 a0 = *(const float4*)&sW[ci][ky*3+kx][tc*8];
                    float4 a1 = *(const float4*)&sW[ci][ky*3+kx][tc*8 + 4];
                    float av[8] = {a0.x,a0.y,a0.z,a0.w,a1.x,a1.y,a1.z,a1.w};
#pragma unroll
                    for (int c = 0; c < 8; c++)
#pragma unroll
                        for (int j = 0; j < 4; j++)
                            acc[c][j] += av[c]*bv[j+kx];
                }
            }
        }
        __syncthreads();
    }
#pragma unroll
    for (int c = 0; c < 8; c++) {
        int co = co0 + tc*8 + c;
        float bs = bias[co];
        float4 o = {acc[c][0]+bs, acc[c][1]+bs, acc[c][2]+bs, acc[c][3]+bs};
        *(float4*)&out[(((size_t)(b*96 + co)) << 14) + (h << 7) + w0] = o;
    }
}

// ---------------- GroupNorm reduce (deterministic, 2-stage) ------------------
__global__ __launch_bounds__(256) void gn_reduce_k(
    const float* __restrict__ x, float* __restrict__ partials)
{
    int bg = blockIdx.x, chunk = blockIdx.y;
    const float4* p = (const float4*)(x + (size_t)bg*GN_N + (size_t)chunk*49152);
    float sx=0,sy=0,sz=0,sw=0, qx=0,qy=0,qz=0,qw=0;
    for (int i = threadIdx.x; i < 12288; i += 256) {
        float4 v = p[i];
        sx += v.x; sy += v.y; sz += v.z; sw += v.w;
        qx += v.x*v.x; qy += v.y*v.y; qz += v.z*v.z; qw += v.w*v.w;
    }
    __shared__ double sh[512];
    int tid = threadIdx.x;
    sh[tid]       = (double)sx + sy + sz + sw;
    sh[256 + tid] = (double)qx + qy + qz + qw;
    __syncthreads();
    for (int st = 128; st > 0; st >>= 1) {
        if (tid < st) { sh[tid] += sh[tid+st]; sh[256+tid] += sh[256+tid+st]; }
        __syncthreads();
    }
    if (tid == 0) {
        partials[(bg*8 + chunk)*2 + 0] = (float)sh[0];
        partials[(bg*8 + chunk)*2 + 1] = (float)sh[256];
    }
}

__global__ void gn_finalize_k(const float* __restrict__ partials,
                              float* __restrict__ stats)
{
    int bg = threadIdx.x;
    float s = 0, q = 0;
    for (int c = 0; c < 8; c++) {
        s += partials[(bg*8 + c)*2 + 0];
        q += partials[(bg*8 + c)*2 + 1];
    }
    float mean = s * (1.f/393216.f);
    float var  = q * (1.f/393216.f) - mean*mean;
    stats[bg*2 + 0] = mean;
    stats[bg*2 + 1] = rsqrtf(var + 1e-5f);
}

// ---------------- time-embedding MLP -----------------------------------------
__global__ void temb_k(const float* __restrict__ te, const float* __restrict__ wt,
                       const float* __restrict__ bt, float* __restrict__ film)
{
    __shared__ float sh[256];
    int b = blockIdx.x, j = threadIdx.x;
    for (int i = threadIdx.x; i < 256; i += 192) sh[i] = te[b*256 + i];
    __syncthreads();
    const float* wr = wt + j*256;
    float s = bt[j];
#pragma unroll 4
    for (int k = 0; k < 256; k++) s += sh[k]*wr[k];
    s = s / (1.f + expf(-s));
    film[b*192 + j] = s;
}

// ---------------- apply GN1 + SiLU + FiLM  (buf1 -> R) -----------------------
__global__ __launch_bounds__(256) void apply1_k(
    const float* __restrict__ x, const float* __restrict__ stats,
    const float* __restrict__ g1, const float* __restrict__ be1,
    const float* __restrict__ film, float* __restrict__ out)
{
    int idx4 = blockIdx.x*256 + threadIdx.x;
    if (idx4 >= NPIX/4) return;
    int flat = idx4 << 2;
    int cimg = flat >> 14;
    int b = cimg / 96, c = cimg - 96*b;
    int bg = b*4 + c/24;
    float mean = stats[bg*2], rstd = stats[bg*2+1];
    float gam = g1[c]*rstd;
    float bet = be1[c] - mean*gam;
    float shf = 1.f + film[b*192 + c];
    float bia = film[b*192 + 96 + c];
    float4 v = *(const float4*)&x[flat];
    float t;
    t = v.x*gam + bet; t = t/(1.f+expf(-t)); v.x = t*shf + bia;
    t = v.y*gam + bet; t = t/(1.f+expf(-t)); v.y = t*shf + bia;
    t = v.z*gam + bet; t = t/(1.f+expf(-t)); v.z = t*shf + bia;
    t = v.w*gam + bet; t = t/(1.f+expf(-t)); v.w = t*shf + bia;
    *(float4*)&out[flat] = v;
}

// ---------------- final: SiLU(GN(conv2)) -> d_out ----------------------------
__global__ __launch_bounds__(256) void apply3_k(
    const float* __restrict__ x, const float* __restrict__ stats,
    const float* __restrict__ g2, const float* __restrict__ be2,
    float* __restrict__ out)
{
    int idx4 = blockIdx.x*256 + threadIdx.x;
    if (idx4 >= NPIX/4) return;
    int flat = idx4 << 2;
    int cimg = flat >> 14;
    int b = cimg / 96, c = cimg - 96*b;
    int bg = b*4 + c/24;
    float mean = stats[bg*2], rstd = stats[bg*2+1];
    float gam = g2[c]*rstd;
    float bet = be2[c] - mean*gam;
    float4 v = *(const float4*)&x[flat];
    float t;
    t = v.x*gam + bet; v.x = t/(1.f+expf(-t));
    t = v.y*gam + bet; v.y = t/(1.f+expf(-t));
    t = v.z*gam + bet; v.z = t/(1.f+expf(-t));
    t = v.w*gam + bet; v.w = t/(1.f+expf(-t));
    *(float4*)&out[flat] = v;
}

// ---------------- qkv 1x1 GEMM with fused GN2 (288 x 96 @ pixels) ------------
// grid (128 h, 9 co-groups, 16 b), 128 threads, thread 8co x 4w
__global__ __launch_bounds__(128) void qkv_k(
    const float* __restrict__ R, const float* __restrict__ stats,
    const float* __restrict__ ga, const float* __restrict__ ba,
    const float* __restrict__ qw, const float* __restrict__ qb,
    float* __restrict__ out)
{
    __shared__ float sIn[16][128];
    __shared__ float sW[16][32];
    int h = blockIdx.x, co0 = blockIdx.y*32, b = blockIdx.z;
    int tid = threadIdx.x, tc = tid >> 5, tw = tid & 31, w0 = tw*4;

    float acc[8][4];
#pragma unroll
    for (int c = 0; c < 8; c++)
#pragma unroll
        for (int j = 0; j < 4; j++) acc[c][j] = 0.f;

    for (int cc = 0; cc < 96; cc += 16) {
        for (int i = tid; i < 2048; i += 128) {
            int ci = i >> 7, col = i & 127;
            int c = cc + ci, bg = b*4 + c/24;
            float v = R[(((size_t)(b*96 + c)) << 14) + (h << 7) + col];
            sIn[ci][col] = (v - stats[bg*2])*stats[bg*2+1]*ga[c] + ba[c];
        }
        for (int i = tid; i < 512; i += 128) {
            int ci = i >> 5, col = i & 31;
            sW[ci][col] = qw[(co0 + col)*96 + cc + ci];
        }
        __syncthreads();
#pragma unroll
        for (int ci = 0; ci < 16; ci++) {
            float4 bv = *(const float4*)&sIn[ci][w0];
            float bb[4] = {bv.x, bv.y, bv.z, bv.w};
            float4 a0 = *(const float4*)&sW[ci][tc*8];
            float4 a1 = *(const float4*)&sW[ci][tc*8 + 4];
            float av[8] = {a0.x,a0.y,a0.z,a0.w,a1.x,a1.y,a1.z,a1.w};
#pragma unroll
            for (int c = 0; c < 8; c++)
#pragma unroll
                for (int j = 0; j < 4; j++)
                    acc[c][j] += av[c]*bb[j];
        }
        __syncthreads();
    }
#pragma unroll
    for (int c = 0; c < 8; c++) {
        int sc = co0 + tc*8 + c;
        float bs = qb[sc];
        float4 o = {acc[c][0]+bs, acc[c][1]+bs, acc[c][2]+bs, acc[c][3]+bs};
        *(float4*)&out[(((size_t)(b*288 + sc)) << 14) + (h << 7) + w0] = o;
    }
}

// ---------------- attention core: one block per (window, b, branch) ----------
__global__ __launch_bounds__(256) void attn_core_k(
    const float* __restrict__ qkv, float* __restrict__ o0, float* __restrict__ o1)
{
    extern __shared__ float sm[];
    float* sq   = sm;            // [288][64]
    float* slog = sq + 18432;    // [16*36]
    float* spr  = slog + 576;    // [16*36]

    int b = blockIdx.y, branch = blockIdx.z;
    int hn = blockIdx.x >> 4, wn = blockIdx.x & 15;
    int sh = branch*4;
    int h0 = hn*8 + sh, w0 = wn*8 + sh;
    int tid = threadIdx.x;

    for (int i = tid; i < 4608; i += 256) {
        int c = i >> 4, lq = i & 15, l = lq << 2;
        int gh = (h0 + (l >> 3)) & 127, gw = (w0 + (l & 7)) & 127;
        *(float4*)&sq[(c << 6) + l] =
            *(const float4*)&qkv[(((size_t)(b*288 + c)) << 14) + (gh << 7) + gw];
    }
    __syncthreads();

    const float scale = 0.40824829046386307f;
    for (int i = tid; i < 576; i += 256) {
        int head = i / 36, r = i - head*36, d = r / 6, e = r - d*6;
        const float* qp = &sq[(head*6 + d) << 6];
        const float* kp = &sq[(96 + head*6 + e) << 6];
        float a = 0.f;
#pragma unroll 8
        for (int l = 0; l < 64; l++) a += qp[l]*kp[l];
        slog[i] = a*scale;
    }
    __syncthreads();

    if (tid < 96) {
        int head = tid / 6, d = tid - head*6, base = head*36 + d*6;
        float m = -1e30f;
#pragma unroll
        for (int e = 0; e < 6; e++) m = fmaxf(m, slog[base+e]);
        float ex[6]; float s = 0.f;
#pragma unroll
        for (int e = 0; e < 6; e++) { ex[e] = expf(slog[base+e] - m); s += ex[e]; }
        float inv = 1.f/s;
#pragma unroll
        for (int e = 0; e < 6; e++) spr[base+e] = ex[e]*inv;
    }
    __syncthreads();

    float* o = branch ? o1 : o0;
    for (int i = tid; i < 1536; i += 256) {
        int ch = i >> 4, lq = i & 15, l = lq << 2;
        int head = ch / 6, d = ch - head*6;
        float4 a = {0.f, 0.f, 0.f, 0.f};
#pragma unroll
        for (int e = 0; e < 6; e++) {
            float p = spr[head*36 + d*6 + e];
            float4 vv = *(const float4*)&sq[((192 + head*6 + e) << 6) + l];
            a.x += p*vv.x; a.y += p*vv.y; a.z += p*vv.z; a.w += p*vv.w;
        }
        int gh = (h0 + (l >> 3)) & 127, gw = (w0 + (l & 7)) & 127;
        *(float4*)&o[(((size_t)(b*96 + ch)) << 14) + (gh << 7) + gw] = a;
    }
}

// ---------------- proj 1x1 GEMM + residual: A = R + 0.5*W@(o0+o1) + pb -------
__global__ __launch_bounds__(128) void proj_k(
    const float* __restrict__ o0, const float* __restrict__ o1,
    const float* __restrict__ R,
    const float* __restrict__ pw, const float* __restrict__ pb,
    float* __restrict__ A)
{
    __shared__ float sIn[16][128];
    __shared__ float sW[16][32];
    int h = blockIdx.x, co0 = blockIdx.y*32, b = blockIdx.z;
    int tid = threadIdx.x, tc = tid >> 5, tw = tid & 31, w0 = tw*4;

    float acc[8][4];
#pragma unroll
    for (int c = 0; c < 8; c++)
#pragma unroll
        for (int j = 0; j < 4; j++) acc[c][j] = 0.f;

    for (int cc = 0; cc < 96; cc += 16) {
        for (int i = tid; i < 2048; i += 128) {
            int ci = i >> 7, col = i & 127;
            size_t idx = (((size_t)(b*96 + cc + ci)) << 14) + (h << 7) + col;
            sIn[ci][col] = o0[idx] + o1[idx];
        }
        for (int i = tid; i < 512; i += 128) {
            int ci = i >> 5, col = i & 31;
            sW[ci][col] = pw[(co0 + col)*96 + cc + ci];
        }
        __syncthreads();
#pragma unroll
        for (int ci = 0; ci < 16; ci++) {
            float4 bv = *(const float4*)&sIn[ci][w0];
            float bb[4] = {bv.x, bv.y, bv.z, bv.w};
            float4 a0 = *(const float4*)&sW[ci][tc*8];
            float4 a1 = *(const float4*)&sW[ci][tc*8 + 4];
            float av[8] = {a0.x,a0.y,a0.z,a0.w,a1.x,a1.y,a1.z,a1.w};
#pragma unroll
            for (int c = 0; c < 8; c++)
#pragma unroll
                for (int j = 0; j < 4; j++)
                    acc[c][j] += av[c]*bb[j];
        }
        __syncthreads();
    }
#pragma unroll
    for (int c = 0; c < 8; c++) {
        int co = co0 + tc*8 + c;
        float bs = pb[co];
        size_t idx = (((size_t)(b*96 + co)) << 14) + (h << 7) + w0;
        float4 r = *(const float4*)&R[idx];
        float4 o = {r.x + 0.5f*acc[c][0] + bs, r.y + 0.5f*acc[c][1] + bs,
                    r.z + 0.5f*acc[c][2] + bs, r.w + 0.5f*acc[c][3] + bs};
        *(float4*)&A[idx] = o;
    }
}

// ---------------- launch -----------------------------------------------------
extern "C" void kernel_launch(void* const* d_in, const int* in_sizes, int n_in,
                              void* d_out, int out_size)
{
    const float* x      = (const float*)d_in[0];
    const float* t_emb  = (const float*)d_in[1];
    const float* w1     = (const float*)d_in[2];
    const float* b1     = (const float*)d_in[3];
    const float* g1     = (const float*)d_in[4];
    const float* be1    = (const float*)d_in[5];
    const float* wt     = (const float*)d_in[6];
    const float* bt     = (const float*)d_in[7];
    const float* qkv_w  = (const float*)d_in[8];
    const float* qkv_b  = (const float*)d_in[9];
    const float* proj_w = (const float*)d_in[10];
    const float* proj_b = (const float*)d_in[11];
    const float* ga     = (const float*)d_in[12];
    const float* ba     = (const float*)d_in[13];
    const float* w2     = (const float*)d_in[14];
    const float* b2     = (const float*)d_in[15];
    const float* g2     = (const float*)d_in[16];
    const float* be2    = (const float*)d_in[17];
    float* out = (float*)d_out;

    float *buf1, *buf2, *buf3, *buf4, *qkvb, *partials, *stats, *film;
    cudaGetSymbolAddress((void**)&buf1, g_buf1);
    cudaGetSymbolAddress((void**)&buf2, g_buf2);
    cudaGetSymbolAddress((void**)&buf3, g_buf3);
    cudaGetSymbolAddress((void**)&buf4, g_buf4);
    cudaGetSymbolAddress((void**)&qkvb, g_qkv);
    cudaGetSymbolAddress((void**)&partials, g_partials);
    cudaGetSymbolAddress((void**)&stats, g_stats);
    cudaGetSymbolAddress((void**)&film, g_film);

    const int ATTN_SMEM = (18432 + 576 + 576) * 4;  // 78,336 B
    cudaFuncSetAttribute(attn_core_k, cudaFuncAttributeMaxDynamicSharedMemorySize,
                         ATTN_SMEM);

    dim3 cgrid(128, 3, 16);
    dim3 rgrid(64, 8);

    // conv1
    conv3x3_k<<<cgrid, 128>>>(x, w1, b1, buf1);
    // GN1 stats
    gn_reduce_k<<<rgrid, 256>>>(buf1, partials + 0*64*8*2);
    gn_finalize_k<<<1, 64>>>(partials + 0*64*8*2, stats + 0*64*2);
    // FiLM
    temb_k<<<16, 192>>>(t_emb, wt, bt, film);
    // R
    apply1_k<<<NPIX/4/256, 256>>>(buf1, stats + 0*64*2, g1, be1, film, buf2);
    // GN2 stats
    gn_reduce_k<<<rgrid, 256>>>(buf2, partials + 1*64*8*2);
    gn_finalize_k<<<1, 64>>>(partials + 1*64*8*2, stats + 1*64*2);
    // qkv over whole image (GN2 fused)
    qkv_k<<<dim3(128, 9, 16), 128>>>(buf2, stats + 1*64*2, ga, ba,
                                     qkv_w, qkv_b, qkvb);
    // attention cores, both branches in one launch
    attn_core_k<<<dim3(256, 16, 2), 256, ATTN_SMEM>>>(qkvb, buf1, buf4);
    // proj + residual
    proj_k<<<cgrid, 128>>>(buf1, buf4, buf2, proj_w, proj_b, buf3);
    // conv2
    conv3x3_k<<<cgrid, 128>>>(buf3, w2, b2, buf1);
    // GN3 stats
    gn_reduce_k<<<rgrid, 256>>>(buf1, partials + 2*64*8*2);
    gn_finalize_k<<<1, 64>>>(partials + 2*64*8*2, stats + 2*64*2);
    // output
    apply3_k<<<NPIX/4/256, 256>>>(buf1, stats + 2*64*2, g2, be2, out);
}

// round 4
// speedup vs baseline: 2.5252x; 1.5499x over previous
#include <cuda_runtime.h>
#include <cuda_bf16.h>
#include <math.h>
#include <stdint.h>

#define Bn 16
#define Cc 96
#define NPIX (16*96*16384)
#define GN_N 393216

// ---------------- scratch ----------------------------------------------------
__device__ float g_buf1[NPIX];
__device__ float g_buf2[NPIX];
__device__ float g_buf3[NPIX];
__device__ float g_buf4[NPIX];
__device__ float g_qkv[3*NPIX];
__device__ float g_partials[3*64*8*2];
__device__ float g_stats[3*64*2];
__device__ float g_film[16*192];

// ---------------- helpers ----------------------------------------------------
__device__ __forceinline__ void mma16816(float* c, const uint32_t* a,
                                         const uint32_t* b) {
    asm volatile(
        "mma.sync.aligned.m16n8k16.row.col.f32.bf16.bf16.f32 "
        "{%0,%1,%2,%3}, {%4,%5,%6,%7}, {%8,%9}, {%0,%1,%2,%3};"
        : "+f"(c[0]), "+f"(c[1]), "+f"(c[2]), "+f"(c[3])
        : "r"(a[0]), "r"(a[1]), "r"(a[2]), "r"(a[3]), "r"(b[0]), "r"(b[1]));
}
__device__ __forceinline__ uint32_t prmt(uint32_t a, uint32_t b, uint32_t sel) {
    uint32_t r;
    asm("prmt.b32 %0, %1, %2, %3;" : "=r"(r) : "r"(a), "r"(b), "r"(sel));
    return r;
}
__device__ __forceinline__ uint32_t split_pack(float v0, float v1) {
    // returns (hi(v0) | hi(v1)<<16) ... caller-specific; not used
    return 0;
}

// ---------------- conv3x3 via mma.sync bf16 3-split --------------------------
// grid (128 h, 16 b), 256 threads (8 warps). D[p=128][co=96].
// Warp tile: 32 p x 48 co = 2 x 6 m16n8k16 tiles.
#define ROW_STRIDE 132                       // u32 words per ci row (conflict-free)
#define OFF_ROW  0                           // u32 rowbuf[96*132]       = 50688 B
#define OFF_BH   50688                       // u32 sBhi[96*52]          = 19968 B
#define OFF_BL   (50688+19968)               // u32 sBlo[96*52]          = 19968 B
#define OFF_CBIAS (OFF_BL+19968)             // float bias[96]           =   384 B
#define CONV_SMEM (OFF_CBIAS + 384)          // 91,008 B

__global__ __launch_bounds__(256) void conv3x3_mma_k(
    const float* __restrict__ in, const float* __restrict__ w,
    const float* __restrict__ bias, float* __restrict__ out)
{
    extern __shared__ char smem[];
    uint32_t* rowbuf = (uint32_t*)(smem + OFF_ROW);
    uint32_t* sBhi   = (uint32_t*)(smem + OFF_BH);
    uint32_t* sBlo   = (uint32_t*)(smem + OFF_BL);
    float*    sbias  = (float*)(smem + OFF_CBIAS);

    int tid = threadIdx.x, wid = tid >> 5, lane = tid & 31;
    int gid = lane >> 2, tig = lane & 3;
    int h = blockIdx.x, b = blockIdx.y;
    int m0 = (wid & 3) * 32;          // pixel tile base
    int n0 = (wid >> 2) * 48;         // co tile base

    float acc[12][4];
#pragma unroll
    for (int t = 0; t < 12; t++)
#pragma unroll
        for (int r = 0; r < 4; r++) acc[t][r] = 0.f;

    for (int i = tid; i < 96; i += 256) sbias[i] = bias[i];

    for (int ky = 0; ky < 3; ky++) {
        int gh = h + ky - 1;
        __syncthreads();   // rowbuf readers from previous ky done
        // stage input row: rowbuf[ci][col] = hi|lo<<16, col = gw+1 in 0..129
        for (int i = tid; i < 96*130; i += 256) {
            int ci = i / 130, col = i - ci*130;
            int gw = col - 1;
            float v = 0.f;
            if ((unsigned)gh < 128u && (unsigned)gw < 128u)
                v = in[(((size_t)(b*96 + ci)) << 14) + (gh << 7) + gw];
            __nv_bfloat16 hi = __float2bfloat16(v);
            __nv_bfloat16 lo = __float2bfloat16(v - __bfloat162float(hi));
            rowbuf[ci*ROW_STRIDE + col] = (uint32_t)__bfloat16_as_ushort(hi)
                                        | ((uint32_t)__bfloat16_as_ushort(lo) << 16);
        }

        for (int kx = 0; kx < 3; kx++) {
            __syncthreads();   // prev k-step readers done; rowbuf staged (first kx)
            // stage weights for (ky,kx): sB[co][k2] = pack(ci=2k2, ci=2k2+1)
            for (int i = tid; i < 96*48; i += 256) {
                int co = i / 48, k2 = i - co*48;
                int ci = k2 << 1;
                float w0v = w[(co*96 + ci)*9 + ky*3 + kx];
                float w1v = w[(co*96 + ci + 1)*9 + ky*3 + kx];
                __nv_bfloat16 h0 = __float2bfloat16(w0v);
                __nv_bfloat16 l0 = __float2bfloat16(w0v - __bfloat162float(h0));
                __nv_bfloat16 h1 = __float2bfloat16(w1v);
                __nv_bfloat16 l1 = __float2bfloat16(w1v - __bfloat162float(h1));
                sBhi[co*52 + k2] = (uint32_t)__bfloat16_as_ushort(h0)
                                 | ((uint32_t)__bfloat16_as_ushort(h1) << 16);
                sBlo[co*52 + k2] = (uint32_t)__bfloat16_as_ushort(l0)
                                 | ((uint32_t)__bfloat16_as_ushort(l1) << 16);
            }
            __syncthreads();

#pragma unroll
            for (int kc = 0; kc < 6; kc++) {        // ci0 = kc*16
                int ci0 = kc << 4;
                // A fragments: [mt][r] r=0..3 => (row+0,ci+0)(row+8,ci+0)(row+0,ci+8)(row+8,ci+8)
                uint32_t ahi[8], alo[8];
#pragma unroll
                for (int mt = 0; mt < 2; mt++) {
                    int colp = m0 + mt*16 + gid + kx;
#pragma unroll
                    for (int r = 0; r < 4; r++) {
                        int prow = colp + ((r & 1) << 3);
                        int cio  = ci0 + (tig << 1) + ((r >> 1) << 3);
                        uint32_t v0 = rowbuf[cio*ROW_STRIDE + prow];
                        uint32_t v1 = rowbuf[(cio+1)*ROW_STRIDE + prow];
                        ahi[mt*4 + r] = prmt(v0, v1, 0x5410);
                        alo[mt*4 + r] = prmt(v0, v1, 0x7632);
                    }
                }
                // B fragments
                uint32_t bhi[12], blo[12];
#pragma unroll
                for (int nt = 0; nt < 6; nt++) {
                    int co = n0 + nt*8 + gid;
                    int k2 = (kc << 3) + tig;
                    bhi[nt*2]   = sBhi[co*52 + k2];
                    bhi[nt*2+1] = sBhi[co*52 + k2 + 4];
                    blo[nt*2]   = sBlo[co*52 + k2];
                    blo[nt*2+1] = sBlo[co*52 + k2 + 4];
                }
                // 3-product split MMA
#pragma unroll
                for (int mt = 0; mt < 2; mt++)
#pragma unroll
                    for (int nt = 0; nt < 6; nt++) {
                        float* c = acc[mt*6 + nt];
                        mma16816(c, &ahi[mt*4], &bhi[nt*2]);
                        mma16816(c, &ahi[mt*4], &blo[nt*2]);
                        mma16816(c, &alo[mt*4], &bhi[nt*2]);
                    }
            }
        }
    }

    // epilogue: C[row=p][col=co] -> out[b][co][h][p]
    size_t obase = (((size_t)(b*96)) << 14) + (h << 7);
#pragma unroll
    for (int mt = 0; mt < 2; mt++) {
        int p = m0 + mt*16 + gid;
#pragma unroll
        for (int nt = 0; nt < 6; nt++) {
            int co = n0 + nt*8 + (tig << 1);
            float* c = acc[mt*6 + nt];
            float bs0 = sbias[co], bs1 = sbias[co+1];
            out[obase + (((size_t)co)   << 14) + p]     = c[0] + bs0;
            out[obase + (((size_t)co+1) << 14) + p]     = c[1] + bs1;
            out[obase + (((size_t)co)   << 14) + p + 8] = c[2] + bs0;
            out[obase + (((size_t)co+1) << 14) + p + 8] = c[3] + bs1;
        }
    }
}

// ---------------- GroupNorm reduce -------------------------------------------
__global__ __launch_bounds__(256) void gn_reduce_k(
    const float* __restrict__ x, float* __restrict__ partials)
{
    int bg = blockIdx.x, chunk = blockIdx.y;
    const float4* p = (const float4*)(x + (size_t)bg*GN_N + (size_t)chunk*49152);
    float sx=0,sy=0,sz=0,sw=0, qx=0,qy=0,qz=0,qw=0;
    for (int i = threadIdx.x; i < 12288; i += 256) {
        float4 v = p[i];
        sx += v.x; sy += v.y; sz += v.z; sw += v.w;
        qx += v.x*v.x; qy += v.y*v.y; qz += v.z*v.z; qw += v.w*v.w;
    }
    __shared__ double sh[512];
    int tid = threadIdx.x;
    sh[tid]       = (double)sx + sy + sz + sw;
    sh[256 + tid] = (double)qx + qy + qz + qw;
    __syncthreads();
    for (int st = 128; st > 0; st >>= 1) {
        if (tid < st) { sh[tid] += sh[tid+st]; sh[256+tid] += sh[256+tid+st]; }
        __syncthreads();
    }
    if (tid == 0) {
        partials[(bg*8 + chunk)*2 + 0] = (float)sh[0];
        partials[(bg*8 + chunk)*2 + 1] = (float)sh[256];
    }
}

__global__ void gn_finalize_k(const float* __restrict__ partials,
                              float* __restrict__ stats)
{
    int bg = threadIdx.x;
    float s = 0, q = 0;
    for (int c = 0; c < 8; c++) {
        s += partials[(bg*8 + c)*2 + 0];
        q += partials[(bg*8 + c)*2 + 1];
    }
    float mean = s * (1.f/393216.f);
    float var  = q * (1.f/393216.f) - mean*mean;
    stats[bg*2 + 0] = mean;
    stats[bg*2 + 1] = rsqrtf(var + 1e-5f);
}

// ---------------- time-embedding MLP -----------------------------------------
__global__ void temb_k(const float* __restrict__ te, const float* __restrict__ wt,
                       const float* __restrict__ bt, float* __restrict__ film)
{
    __shared__ float sh[256];
    int b = blockIdx.x, j = threadIdx.x;
    for (int i = threadIdx.x; i < 256; i += 192) sh[i] = te[b*256 + i];
    __syncthreads();
    const float* wr = wt + j*256;
    float s = bt[j];
#pragma unroll 4
    for (int k = 0; k < 256; k++) s += sh[k]*wr[k];
    s = s / (1.f + expf(-s));
    film[b*192 + j] = s;
}

// ---------------- apply GN1 + SiLU + FiLM ------------------------------------
__global__ __launch_bounds__(256) void apply1_k(
    const float* __restrict__ x, const float* __restrict__ stats,
    const float* __restrict__ g1, const float* __restrict__ be1,
    const float* __restrict__ film, float* __restrict__ out)
{
    int idx4 = blockIdx.x*256 + threadIdx.x;
    if (idx4 >= NPIX/4) return;
    int flat = idx4 << 2;
    int cimg = flat >> 14;
    int b = cimg / 96, c = cimg - 96*b;
    int bg = b*4 + c/24;
    float mean = stats[bg*2], rstd = stats[bg*2+1];
    float gam = g1[c]*rstd;
    float bet = be1[c] - mean*gam;
    float shf = 1.f + film[b*192 + c];
    float bia = film[b*192 + 96 + c];
    float4 v = *(const float4*)&x[flat];
    float t;
    t = v.x*gam + bet; t = t/(1.f+expf(-t)); v.x = t*shf + bia;
    t = v.y*gam + bet; t = t/(1.f+expf(-t)); v.y = t*shf + bia;
    t = v.z*gam + bet; t = t/(1.f+expf(-t)); v.z = t*shf + bia;
    t = v.w*gam + bet; t = t/(1.f+expf(-t)); v.w = t*shf + bia;
    *(float4*)&out[flat] = v;
}

// ---------------- final: SiLU(GN(conv2)) -> d_out ----------------------------
__global__ __launch_bounds__(256) void apply3_k(
    const float* __restrict__ x, const float* __restrict__ stats,
    const float* __restrict__ g2, const float* __restrict__ be2,
    float* __restrict__ out)
{
    int idx4 = blockIdx.x*256 + threadIdx.x;
    if (idx4 >= NPIX/4) return;
    int flat = idx4 << 2;
    int cimg = flat >> 14;
    int b = cimg / 96, c = cimg - 96*b;
    int bg = b*4 + c/24;
    float mean = stats[bg*2], rstd = stats[bg*2+1];
    float gam = g2[c]*rstd;
    float bet = be2[c] - mean*gam;
    float4 v = *(const float4*)&x[flat];
    float t;
    t = v.x*gam + bet; v.x = t/(1.f+expf(-t));
    t = v.y*gam + bet; v.y = t/(1.f+expf(-t));
    t = v.z*gam + bet; v.z = t/(1.f+expf(-t));
    t = v.w*gam + bet; v.w = t/(1.f+expf(-t));
    *(float4*)&out[flat] = v;
}

// ---------------- qkv 1x1 GEMM with fused GN2 --------------------------------
__global__ __launch_bounds__(128) void qkv_k(
    const float* __restrict__ R, const float* __restrict__ stats,
    const float* __restrict__ ga, const float* __restrict__ ba,
    const float* __restrict__ qw, const float* __restrict__ qb,
    float* __restrict__ out)
{
    __shared__ float sIn[16][128];
    __shared__ float sW[16][32];
    int h = blockIdx.x, co0 = blockIdx.y*32, b = blockIdx.z;
    int tid = threadIdx.x, tc = tid >> 5, tw = tid & 31, w0 = tw*4;

    float acc[8][4];
#pragma unroll
    for (int c = 0; c < 8; c++)
#pragma unroll
        for (int j = 0; j < 4; j++) acc[c][j] = 0.f;

    for (int cc = 0; cc < 96; cc += 16) {
        for (int i = tid; i < 2048; i += 128) {
            int ci = i >> 7, col = i & 127;
            int c = cc + ci, bg = b*4 + c/24;
            float v = R[(((size_t)(b*96 + c)) << 14) + (h << 7) + col];
            sIn[ci][col] = (v - stats[bg*2])*stats[bg*2+1]*ga[c] + ba[c];
        }
        for (int i = tid; i < 512; i += 128) {
            int ci = i >> 5, col = i & 31;
            sW[ci][col] = qw[(co0 + col)*96 + cc + ci];
        }
        __syncthreads();
#pragma unroll
        for (int ci = 0; ci < 16; ci++) {
            float4 bv = *(const float4*)&sIn[ci][w0];
            float bb[4] = {bv.x, bv.y, bv.z, bv.w};
            float4 a0 = *(const float4*)&sW[ci][tc*8];
            float4 a1 = *(const float4*)&sW[ci][tc*8 + 4];
            float av[8] = {a0.x,a0.y,a0.z,a0.w,a1.x,a1.y,a1.z,a1.w};
#pragma unroll
            for (int c = 0; c < 8; c++)
#pragma unroll
                for (int j = 0; j < 4; j++)
                    acc[c][j] += av[c]*bb[j];
        }
        __syncthreads();
    }
#pragma unroll
    for (int c = 0; c < 8; c++) {
        int sc = co0 + tc*8 + c;
        float bs = qb[sc];
        float4 o = {acc[c][0]+bs, acc[c][1]+bs, acc[c][2]+bs, acc[c][3]+bs};
        *(float4*)&out[(((size_t)(b*288 + sc)) << 14) + (h << 7) + w0] = o;
    }
}

// ---------------- attention core ---------------------------------------------
__global__ __launch_bounds__(256) void attn_core_k(
    const float* __restrict__ qkv, float* __restrict__ o0, float* __restrict__ o1)
{
    extern __shared__ float sm[];
    float* sq   = sm;
    float* slog = sq + 18432;
    float* spr  = slog + 576;

    int b = blockIdx.y, branch = blockIdx.z;
    int hn = blockIdx.x >> 4, wn = blockIdx.x & 15;
    int sh = branch*4;
    int h0 = hn*8 + sh, w0 = wn*8 + sh;
    int tid = threadIdx.x;

    for (int i = tid; i < 4608; i += 256) {
        int c = i >> 4, lq = i & 15, l = lq << 2;
        int gh = (h0 + (l >> 3)) & 127, gw = (w0 + (l & 7)) & 127;
        *(float4*)&sq[(c << 6) + l] =
            *(const float4*)&qkv[(((size_t)(b*288 + c)) << 14) + (gh << 7) + gw];
    }
    __syncthreads();

    const float scale = 0.40824829046386307f;
    for (int i = tid; i < 576; i += 256) {
        int head = i / 36, r = i - head*36, d = r / 6, e = r - d*6;
        const float* qp = &sq[(head*6 + d) << 6];
        const float* kp = &sq[(96 + head*6 + e) << 6];
        float a = 0.f;
#pragma unroll 8
        for (int l = 0; l < 64; l++) a += qp[l]*kp[l];
        slog[i] = a*scale;
    }
    __syncthreads();

    if (tid < 96) {
        int head = tid / 6, d = tid - head*6, base = head*36 + d*6;
        float m = -1e30f;
#pragma unroll
        for (int e = 0; e < 6; e++) m = fmaxf(m, slog[base+e]);
        float ex[6]; float s = 0.f;
#pragma unroll
        for (int e = 0; e < 6; e++) { ex[e] = expf(slog[base+e] - m); s += ex[e]; }
        float inv = 1.f/s;
#pragma unroll
        for (int e = 0; e < 6; e++) spr[base+e] = ex[e]*inv;
    }
    __syncthreads();

    float* o = branch ? o1 : o0;
    for (int i = tid; i < 1536; i += 256) {
        int ch = i >> 4, lq = i & 15, l = lq << 2;
        int head = ch / 6, d = ch - head*6;
        float4 a = {0.f, 0.f, 0.f, 0.f};
#pragma unroll
        for (int e = 0; e < 6; e++) {
            float p = spr[head*36 + d*6 + e];
            float4 vv = *(const float4*)&sq[((192 + head*6 + e) << 6) + l];
            a.x += p*vv.x; a.y += p*vv.y; a.z += p*vv.z; a.w += p*vv.w;
        }
        int gh = (h0 + (l >> 3)) & 127, gw = (w0 + (l & 7)) & 127;
        *(float4*)&o[(((size_t)(b*96 + ch)) << 14) + (gh << 7) + gw] = a;
    }
}

// ---------------- proj 1x1 + residual ----------------------------------------
__global__ __launch_bounds__(128) void proj_k(
    const float* __restrict__ o0, const float* __restrict__ o1,
    const float* __restrict__ R,
    const float* __restrict__ pw, const float* __restrict__ pb,
    float* __restrict__ A)
{
    __shared__ float sIn[16][128];
    __shared__ float sW[16][32];
    int h = blockIdx.x, co0 = blockIdx.y*32, b = blockIdx.z;
    int tid = threadIdx.x, tc = tid >> 5, tw = tid & 31, w0 = tw*4;

    float acc[8][4];
#pragma unroll
    for (int c = 0; c < 8; c++)
#pragma unroll
        for (int j = 0; j < 4; j++) acc[c][j] = 0.f;

    for (int cc = 0; cc < 96; cc += 16) {
        for (int i = tid; i < 2048; i += 128) {
            int ci = i >> 7, col = i & 127;
            size_t idx = (((size_t)(b*96 + cc + ci)) << 14) + (h << 7) + col;
            sIn[ci][col] = o0[idx] + o1[idx];
        }
        for (int i = tid; i < 512; i += 128) {
            int ci = i >> 5, col = i & 31;
            sW[ci][col] = pw[(co0 + col)*96 + cc + ci];
        }
        __syncthreads();
#pragma unroll
        for (int ci = 0; ci < 16; ci++) {
            float4 bv = *(const float4*)&sIn[ci][w0];
            float bb[4] = {bv.x, bv.y, bv.z, bv.w};
            float4 a0 = *(const float4*)&sW[ci][tc*8];
            float4 a1 = *(const float4*)&sW[ci][tc*8 + 4];
            float av[8] = {a0.x,a0.y,a0.z,a0.w,a1.x,a1.y,a1.z,a1.w};
#pragma unroll
            for (int c = 0; c < 8; c++)
#pragma unroll
                for (int j = 0; j < 4; j++)
                    acc[c][j] += av[c]*bb[j];
        }
        __syncthreads();
    }
#pragma unroll
    for (int c = 0; c < 8; c++) {
        int co = co0 + tc*8 + c;
        float bs = pb[co];
        size_t idx = (((size_t)(b*96 + co)) << 14) + (h << 7) + w0;
        float4 r = *(const float4*)&R[idx];
        float4 o = {r.x + 0.5f*acc[c][0] + bs, r.y + 0.5f*acc[c][1] + bs,
                    r.z + 0.5f*acc[c][2] + bs, r.w + 0.5f*acc[c][3] + bs};
        *(float4*)&A[idx] = o;
    }
}

// ---------------- launch -----------------------------------------------------
extern "C" void kernel_launch(void* const* d_in, const int* in_sizes, int n_in,
                              void* d_out, int out_size)
{
    const float* x      = (const float*)d_in[0];
    const float* t_emb  = (const float*)d_in[1];
    const float* w1     = (const float*)d_in[2];
    const float* b1     = (const float*)d_in[3];
    const float* g1     = (const float*)d_in[4];
    const float* be1    = (const float*)d_in[5];
    const float* wt     = (const float*)d_in[6];
    const float* bt     = (const float*)d_in[7];
    const float* qkv_w  = (const float*)d_in[8];
    const float* qkv_b  = (const float*)d_in[9];
    const float* proj_w = (const float*)d_in[10];
    const float* proj_b = (const float*)d_in[11];
    const float* ga     = (const float*)d_in[12];
    const float* ba     = (const float*)d_in[13];
    const float* w2     = (const float*)d_in[14];
    const float* b2     = (const float*)d_in[15];
    const float* g2     = (const float*)d_in[16];
    const float* be2    = (const float*)d_in[17];
    float* out = (float*)d_out;

    float *buf1, *buf2, *buf3, *buf4, *qkvb, *partials, *stats, *film;
    cudaGetSymbolAddress((void**)&buf1, g_buf1);
    cudaGetSymbolAddress((void**)&buf2, g_buf2);
    cudaGetSymbolAddress((void**)&buf3, g_buf3);
    cudaGetSymbolAddress((void**)&buf4, g_buf4);
    cudaGetSymbolAddress((void**)&qkvb, g_qkv);
    cudaGetSymbolAddress((void**)&partials, g_partials);
    cudaGetSymbolAddress((void**)&stats, g_stats);
    cudaGetSymbolAddress((void**)&film, g_film);

    const int ATTN_SMEM = (18432 + 576 + 576) * 4;
    cudaFuncSetAttribute(attn_core_k, cudaFuncAttributeMaxDynamicSharedMemorySize,
                         ATTN_SMEM);
    cudaFuncSetAttribute(conv3x3_mma_k, cudaFuncAttributeMaxDynamicSharedMemorySize,
                         CONV_SMEM);

    dim3 cgrid(128, 16);
    dim3 rgrid(64, 8);

    // conv1 (mma.sync bf16 3-split)
    conv3x3_mma_k<<<cgrid, 256, CONV_SMEM>>>(x, w1, b1, buf1);
    // GN1 stats
    gn_reduce_k<<<rgrid, 256>>>(buf1, partials + 0*64*8*2);
    gn_finalize_k<<<1, 64>>>(partials + 0*64*8*2, stats + 0*64*2);
    // FiLM
    temb_k<<<16, 192>>>(t_emb, wt, bt, film);
    // R
    apply1_k<<<NPIX/4/256, 256>>>(buf1, stats + 0*64*2, g1, be1, film, buf2);
    // GN2 stats
    gn_reduce_k<<<rgrid, 256>>>(buf2, partials + 1*64*8*2);
    gn_finalize_k<<<1, 64>>>(partials + 1*64*8*2, stats + 1*64*2);
    // qkv (GN2 fused)
    qkv_k<<<dim3(128, 9, 16), 128>>>(buf2, stats + 1*64*2, ga, ba,
                                     qkv_w, qkv_b, qkvb);
    // attention cores, both branches
    attn_core_k<<<dim3(256, 16, 2), 256, ATTN_SMEM>>>(qkvb, buf1, buf4);
    // proj + residual
    proj_k<<<dim3(128, 3, 16), 128>>>(buf1, buf4, buf2, proj_w, proj_b, buf3);
    // conv2 (mma.sync)
    conv3x3_mma_k<<<cgrid, 256, CONV_SMEM>>>(buf3, w2, b2, buf1);
    // GN3 stats
    gn_reduce_k<<<rgrid, 256>>>(buf1, partials + 2*64*8*2);
    gn_finalize_k<<<1, 64>>>(partials + 2*64*8*2, stats + 2*64*2);
    // output
    apply3_k<<<NPIX/4/256, 256>>>(buf1, stats + 2*64*2, g2, be2, out);
}

// round 5
// speedup vs baseline: 3.7286x; 1.4766x over previous
#include <cuda_runtime.h>
#include <cuda_bf16.h>
#include <math.h>
#include <stdint.h>

#define Bn 16
#define Cc 96
#define NPIX (16*96*16384)
#define GN_N 393216

// ---------------- scratch ----------------------------------------------------
__device__ float g_buf1[NPIX];
__device__ float g_buf2[NPIX];
__device__ float g_buf3[NPIX];
__device__ float g_buf4[NPIX];
__device__ float g_qkv[3*NPIX];
__device__ float g_partials[3*64*8*2];
__device__ float g_stats[3*64*2];
__device__ float g_film[16*192];
// packed hi/lo bf16-pair weights
__device__ uint32_t g_w1hi[41472], g_w1lo[41472];
__device__ uint32_t g_w2hi[41472], g_w2lo[41472];
__device__ uint32_t g_qwhi[13824], g_qwlo[13824];
__device__ uint32_t g_pwhi[4608],  g_pwlo[4608];

// ---------------- helpers ----------------------------------------------------
__device__ __forceinline__ void mma16816(float* c, const uint32_t* a,
                                         const uint32_t* b) {
    asm volatile(
        "mma.sync.aligned.m16n8k16.row.col.f32.bf16.bf16.f32 "
        "{%0,%1,%2,%3}, {%4,%5,%6,%7}, {%8,%9}, {%0,%1,%2,%3};"
        : "+f"(c[0]), "+f"(c[1]), "+f"(c[2]), "+f"(c[3])
        : "r"(a[0]), "r"(a[1]), "r"(a[2]), "r"(a[3]), "r"(b[0]), "r"(b[1]));
}
__device__ __forceinline__ uint32_t prmt(uint32_t a, uint32_t b, uint32_t sel) {
    uint32_t r;
    asm("prmt.b32 %0, %1, %2, %3;" : "=r"(r) : "r"(a), "r"(b), "r"(sel));
    return r;
}
__device__ __forceinline__ uint32_t packsplit(float v) {
    __nv_bfloat16 hi = __float2bfloat16(v);
    __nv_bfloat16 lo = __float2bfloat16(v - __bfloat162float(hi));
    return (uint32_t)__bfloat16_as_ushort(hi)
         | ((uint32_t)__bfloat16_as_ushort(lo) << 16);
}

// ---------------- weight prepack ---------------------------------------------
// seg 0: w1, 1: w2 (3x3), 2: qkv_w, 3: proj_w (1x1)
__global__ __launch_bounds__(256) void prep_k(
    const float* __restrict__ w1, const float* __restrict__ w2,
    const float* __restrict__ qw, const float* __restrict__ pw)
{
    int seg = blockIdx.y;
    int i = blockIdx.x*256 + threadIdx.x;
    float v0, v1;
    uint32_t *dh, *dl;
    if (seg < 2) {
        if (i >= 41472) return;
        const float* w = seg ? w2 : w1;
        dh = seg ? g_w2hi : g_w1hi;
        dl = seg ? g_w2lo : g_w1lo;
        int kk = i / 4608, r = i - kk*4608;
        int co = r / 48, k2 = r - co*48, ci = k2 << 1;
        v0 = w[(co*96 + ci)*9 + kk];
        v1 = w[(co*96 + ci + 1)*9 + kk];
    } else if (seg == 2) {
        if (i >= 13824) return;
        dh = g_qwhi; dl = g_qwlo;
        int co = i / 48, k2 = i - co*48, ci = k2 << 1;
        v0 = qw[co*96 + ci]; v1 = qw[co*96 + ci + 1];
    } else {
        if (i >= 4608) return;
        dh = g_pwhi; dl = g_pwlo;
        int co = i / 48, k2 = i - co*48, ci = k2 << 1;
        v0 = pw[co*96 + ci]; v1 = pw[co*96 + ci + 1];
    }
    __nv_bfloat16 h0 = __float2bfloat16(v0);
    __nv_bfloat16 l0 = __float2bfloat16(v0 - __bfloat162float(h0));
    __nv_bfloat16 h1 = __float2bfloat16(v1);
    __nv_bfloat16 l1 = __float2bfloat16(v1 - __bfloat162float(h1));
    dh[i] = (uint32_t)__bfloat16_as_ushort(h0) | ((uint32_t)__bfloat16_as_ushort(h1) << 16);
    dl[i] = (uint32_t)__bfloat16_as_ushort(l0) | ((uint32_t)__bfloat16_as_ushort(l1) << 16);
}

// ---------------- conv3x3 via mma.sync bf16 3-split --------------------------
#define ROW_STRIDE 132
#define OFF_ROW  0                           // u32 rowbuf[96*132]
#define OFF_BH   50688                       // u32 sBhi[96*52]
#define OFF_BL   (50688+19968)               // u32 sBlo[96*52]
#define OFF_CBIAS (OFF_BL+19968)             // float bias[96]
#define CONV_SMEM (OFF_CBIAS + 384)          // 91,008 B

__global__ __launch_bounds__(256) void conv3x3_mma_k(
    const float* __restrict__ in, const uint32_t* __restrict__ wphi,
    const uint32_t* __restrict__ wplo,
    const float* __restrict__ bias, float* __restrict__ out)
{
    extern __shared__ char smem[];
    uint32_t* rowbuf = (uint32_t*)(smem + OFF_ROW);
    uint32_t* sBhi   = (uint32_t*)(smem + OFF_BH);
    uint32_t* sBlo   = (uint32_t*)(smem + OFF_BL);
    float*    sbias  = (float*)(smem + OFF_CBIAS);

    int tid = threadIdx.x, wid = tid >> 5, lane = tid & 31;
    int gid = lane >> 2, tig = lane & 3;
    int h = blockIdx.x, b = blockIdx.y;
    int m0 = (wid & 3) * 32;
    int n0 = (wid >> 2) * 48;

    float acc[12][4];
#pragma unroll
    for (int t = 0; t < 12; t++)
#pragma unroll
        for (int r = 0; r < 4; r++) acc[t][r] = 0.f;

    for (int i = tid; i < 96; i += 256) sbias[i] = bias[i];

    for (int ky = 0; ky < 3; ky++) {
        int gh = h + ky - 1;
        __syncthreads();
        for (int i = tid; i < 96*130; i += 256) {
            int ci = i / 130, col = i - ci*130;
            int gw = col - 1;
            float v = 0.f;
            if ((unsigned)gh < 128u && (unsigned)gw < 128u)
                v = in[(((size_t)(b*96 + ci)) << 14) + (gh << 7) + gw];
            rowbuf[ci*ROW_STRIDE + col] = packsplit(v);
        }

        for (int kx = 0; kx < 3; kx++) {
            __syncthreads();
            int kk = ky*3 + kx;
            for (int i = tid; i < 4608; i += 256) {
                int co = i / 48, k2 = i - co*48;
                sBhi[co*52 + k2] = wphi[kk*4608 + i];
                sBlo[co*52 + k2] = wplo[kk*4608 + i];
            }
            __syncthreads();

#pragma unroll
            for (int kc = 0; kc < 6; kc++) {
                int ci0 = kc << 4;
                uint32_t ahi[8], alo[8];
#pragma unroll
                for (int mt = 0; mt < 2; mt++) {
                    int colp = m0 + mt*16 + gid + kx;
#pragma unroll
                    for (int r = 0; r < 4; r++) {
                        int prow = colp + ((r & 1) << 3);
                        int cio  = ci0 + (tig << 1) + ((r >> 1) << 3);
                        uint32_t v0 = rowbuf[cio*ROW_STRIDE + prow];
                        uint32_t v1 = rowbuf[(cio+1)*ROW_STRIDE + prow];
                        ahi[mt*4 + r] = prmt(v0, v1, 0x5410);
                        alo[mt*4 + r] = prmt(v0, v1, 0x7632);
                    }
                }
                uint32_t bhi[12], blo[12];
#pragma unroll
                for (int nt = 0; nt < 6; nt++) {
                    int co = n0 + nt*8 + gid;
                    int k2 = (kc << 3) + tig;
                    bhi[nt*2]   = sBhi[co*52 + k2];
                    bhi[nt*2+1] = sBhi[co*52 + k2 + 4];
                    blo[nt*2]   = sBlo[co*52 + k2];
                    blo[nt*2+1] = sBlo[co*52 + k2 + 4];
                }
#pragma unroll
                for (int mt = 0; mt < 2; mt++)
#pragma unroll
                    for (int nt = 0; nt < 6; nt++) {
                        float* c = acc[mt*6 + nt];
                        mma16816(c, &ahi[mt*4], &bhi[nt*2]);
                        mma16816(c, &ahi[mt*4], &blo[nt*2]);
                        mma16816(c, &alo[mt*4], &bhi[nt*2]);
                    }
            }
        }
    }

    size_t obase = (((size_t)(b*96)) << 14) + (h << 7);
#pragma unroll
    for (int mt = 0; mt < 2; mt++) {
        int p = m0 + mt*16 + gid;
#pragma unroll
        for (int nt = 0; nt < 6; nt++) {
            int co = n0 + nt*8 + (tig << 1);
            float* c = acc[mt*6 + nt];
            float bs0 = sbias[co], bs1 = sbias[co+1];
            out[obase + (((size_t)co)   << 14) + p]     = c[0] + bs0;
            out[obase + (((size_t)co+1) << 14) + p]     = c[1] + bs1;
            out[obase + (((size_t)co)   << 14) + p + 8] = c[2] + bs0;
            out[obase + (((size_t)co+1) << 14) + p + 8] = c[3] + bs1;
        }
    }
}

// ---------------- qkv 1x1 GEMM via mma.sync (GN2 fused into staging) ---------
// grid (128 h, 3 cog, 16 b), 256 threads; block = 128 px x 96 co (cog*96 base)
__global__ __launch_bounds__(256) void qkv_mma_k(
    const float* __restrict__ R, const float* __restrict__ stats,
    const float* __restrict__ ga, const float* __restrict__ ba,
    const uint32_t* __restrict__ qwhi, const uint32_t* __restrict__ qwlo,
    const float* __restrict__ qb, float* __restrict__ out)
{
    extern __shared__ char smem[];
    uint32_t* rowbuf = (uint32_t*)(smem + OFF_ROW);
    uint32_t* sBhi   = (uint32_t*)(smem + OFF_BH);
    uint32_t* sBlo   = (uint32_t*)(smem + OFF_BL);
    float*    sbias  = (float*)(smem + OFF_CBIAS);

    int tid = threadIdx.x, wid = tid >> 5, lane = tid & 31;
    int gid = lane >> 2, tig = lane & 3;
    int h = blockIdx.x, cog = blockIdx.y, b = blockIdx.z;
    int m0 = (wid & 3) * 32;
    int n0 = (wid >> 2) * 48;

    float acc[12][4];
#pragma unroll
    for (int t = 0; t < 12; t++)
#pragma unroll
        for (int r = 0; r < 4; r++) acc[t][r] = 0.f;

    // stage A: normalized R row, split-packed
    for (int i = tid; i < 12288; i += 256) {
        int ci = i >> 7, col = i & 127;
        int bg = b*4 + ci/24;
        float mean = stats[bg*2], rstd = stats[bg*2+1];
        float v = R[(((size_t)(b*96 + ci)) << 14) + (h << 7) + col];
        float xn = (v - mean)*rstd*ga[ci] + ba[ci];
        rowbuf[ci*ROW_STRIDE + col] = packsplit(xn);
    }
    // stage B from prepacked weights
    for (int i = tid; i < 4608; i += 256) {
        int co = i / 48, k2 = i - co*48;
        sBhi[co*52 + k2] = qwhi[cog*4608 + i];
        sBlo[co*52 + k2] = qwlo[cog*4608 + i];
    }
    for (int i = tid; i < 96; i += 256) sbias[i] = qb[cog*96 + i];
    __syncthreads();

#pragma unroll
    for (int kc = 0; kc < 6; kc++) {
        int ci0 = kc << 4;
        uint32_t ahi[8], alo[8];
#pragma unroll
        for (int mt = 0; mt < 2; mt++) {
            int colp = m0 + mt*16 + gid;
#pragma unroll
            for (int r = 0; r < 4; r++) {
                int prow = colp + ((r & 1) << 3);
                int cio  = ci0 + (tig << 1) + ((r >> 1) << 3);
                uint32_t v0 = rowbuf[cio*ROW_STRIDE + prow];
                uint32_t v1 = rowbuf[(cio+1)*ROW_STRIDE + prow];
                ahi[mt*4 + r] = prmt(v0, v1, 0x5410);
                alo[mt*4 + r] = prmt(v0, v1, 0x7632);
            }
        }
        uint32_t bhi[12], blo[12];
#pragma unroll
        for (int nt = 0; nt < 6; nt++) {
            int co = n0 + nt*8 + gid;
            int k2 = (kc << 3) + tig;
            bhi[nt*2]   = sBhi[co*52 + k2];
            bhi[nt*2+1] = sBhi[co*52 + k2 + 4];
            blo[nt*2]   = sBlo[co*52 + k2];
            blo[nt*2+1] = sBlo[co*52 + k2 + 4];
        }
#pragma unroll
        for (int mt = 0; mt < 2; mt++)
#pragma unroll
            for (int nt = 0; nt < 6; nt++) {
                float* c = acc[mt*6 + nt];
                mma16816(c, &ahi[mt*4], &bhi[nt*2]);
                mma16816(c, &ahi[mt*4], &blo[nt*2]);
                mma16816(c, &alo[mt*4], &bhi[nt*2]);
            }
    }

    size_t obase = (((size_t)(b*288 + cog*96)) << 14) + (h << 7);
#pragma unroll
    for (int mt = 0; mt < 2; mt++) {
        int p = m0 + mt*16 + gid;
#pragma unroll
        for (int nt = 0; nt < 6; nt++) {
            int co = n0 + nt*8 + (tig << 1);
            float* c = acc[mt*6 + nt];
            float bs0 = sbias[co], bs1 = sbias[co+1];
            out[obase + (((size_t)co)   << 14) + p]     = c[0] + bs0;
            out[obase + (((size_t)co+1) << 14) + p]     = c[1] + bs1;
            out[obase + (((size_t)co)   << 14) + p + 8] = c[2] + bs0;
            out[obase + (((size_t)co+1) << 14) + p + 8] = c[3] + bs1;
        }
    }
}

// ---------------- proj 1x1 via mma.sync + residual ---------------------------
// grid (128 h, 16 b), 256 threads; A = R + 0.5*W@(o0+o1) + pb
__global__ __launch_bounds__(256) void proj_mma_k(
    const float* __restrict__ o0, const float* __restrict__ o1,
    const float* __restrict__ R,
    const uint32_t* __restrict__ pwhi, const uint32_t* __restrict__ pwlo,
    const float* __restrict__ pb, float* __restrict__ A)
{
    extern __shared__ char smem[];
    uint32_t* rowbuf = (uint32_t*)(smem + OFF_ROW);
    uint32_t* sBhi   = (uint32_t*)(smem + OFF_BH);
    uint32_t* sBlo   = (uint32_t*)(smem + OFF_BL);
    float*    sbias  = (float*)(smem + OFF_CBIAS);

    int tid = threadIdx.x, wid = tid >> 5, lane = tid & 31;
    int gid = lane >> 2, tig = lane & 3;
    int h = blockIdx.x, b = blockIdx.y;
    int m0 = (wid & 3) * 32;
    int n0 = (wid >> 2) * 48;

    float acc[12][4];
#pragma unroll
    for (int t = 0; t < 12; t++)
#pragma unroll
        for (int r = 0; r < 4; r++) acc[t][r] = 0.f;

    for (int i = tid; i < 12288; i += 256) {
        int ci = i >> 7, col = i & 127;
        size_t idx = (((size_t)(b*96 + ci)) << 14) + (h << 7) + col;
        rowbuf[ci*ROW_STRIDE + col] = packsplit(o0[idx] + o1[idx]);
    }
    for (int i = tid; i < 4608; i += 256) {
        int co = i / 48, k2 = i - co*48;
        sBhi[co*52 + k2] = pwhi[i];
        sBlo[co*52 + k2] = pwlo[i];
    }
    for (int i = tid; i < 96; i += 256) sbias[i] = pb[i];
    __syncthreads();

#pragma unroll
    for (int kc = 0; kc < 6; kc++) {
        int ci0 = kc << 4;
        uint32_t ahi[8], alo[8];
#pragma unroll
        for (int mt = 0; mt < 2; mt++) {
            int colp = m0 + mt*16 + gid;
#pragma unroll
            for (int r = 0; r < 4; r++) {
                int prow = colp + ((r & 1) << 3);
                int cio  = ci0 + (tig << 1) + ((r >> 1) << 3);
                uint32_t v0 = rowbuf[cio*ROW_STRIDE + prow];
                uint32_t v1 = rowbuf[(cio+1)*ROW_STRIDE + prow];
                ahi[mt*4 + r] = prmt(v0, v1, 0x5410);
                alo[mt*4 + r] = prmt(v0, v1, 0x7632);
            }
        }
        uint32_t bhi[12], blo[12];
#pragma unroll
        for (int nt = 0; nt < 6; nt++) {
            int co = n0 + nt*8 + gid;
            int k2 = (kc << 3) + tig;
            bhi[nt*2]   = sBhi[co*52 + k2];
            bhi[nt*2+1] = sBhi[co*52 + k2 + 4];
            blo[nt*2]   = sBlo[co*52 + k2];
            blo[nt*2+1] = sBlo[co*52 + k2 + 4];
        }
#pragma unroll
        for (int mt = 0; mt < 2; mt++)
#pragma unroll
            for (int nt = 0; nt < 6; nt++) {
                float* c = acc[mt*6 + nt];
                mma16816(c, &ahi[mt*4], &bhi[nt*2]);
                mma16816(c, &ahi[mt*4], &blo[nt*2]);
                mma16816(c, &alo[mt*4], &bhi[nt*2]);
            }
    }

    size_t obase = (((size_t)(b*96)) << 14) + (h << 7);
#pragma unroll
    for (int mt = 0; mt < 2; mt++) {
        int p = m0 + mt*16 + gid;
#pragma unroll
        for (int nt = 0; nt < 6; nt++) {
            int co = n0 + nt*8 + (tig << 1);
            float* c = acc[mt*6 + nt];
            float bs0 = sbias[co], bs1 = sbias[co+1];
            size_t i00 = obase + (((size_t)co) << 14) + p;
            size_t i10 = obase + (((size_t)co+1) << 14) + p;
            A[i00]     = R[i00]     + 0.5f*c[0] + bs0;
            A[i10]     = R[i10]     + 0.5f*c[1] + bs1;
            A[i00 + 8] = R[i00 + 8] + 0.5f*c[2] + bs0;
            A[i10 + 8] = R[i10 + 8] + 0.5f*c[3] + bs1;
        }
    }
}

// ---------------- GroupNorm reduce -------------------------------------------
__global__ __launch_bounds__(256) void gn_reduce_k(
    const float* __restrict__ x, float* __restrict__ partials)
{
    int bg = blockIdx.x, chunk = blockIdx.y;
    const float4* p = (const float4*)(x + (size_t)bg*GN_N + (size_t)chunk*49152);
    float sx=0,sy=0,sz=0,sw=0, qx=0,qy=0,qz=0,qw=0;
    for (int i = threadIdx.x; i < 12288; i += 256) {
        float4 v = p[i];
        sx += v.x; sy += v.y; sz += v.z; sw += v.w;
        qx += v.x*v.x; qy += v.y*v.y; qz += v.z*v.z; qw += v.w*v.w;
    }
    __shared__ double sh[512];
    int tid = threadIdx.x;
    sh[tid]       = (double)sx + sy + sz + sw;
    sh[256 + tid] = (double)qx + qy + qz + qw;
    __syncthreads();
    for (int st = 128; st > 0; st >>= 1) {
        if (tid < st) { sh[tid] += sh[tid+st]; sh[256+tid] += sh[256+tid+st]; }
        __syncthreads();
    }
    if (tid == 0) {
        partials[(bg*8 + chunk)*2 + 0] = (float)sh[0];
        partials[(bg*8 + chunk)*2 + 1] = (float)sh[256];
    }
}

__global__ void gn_finalize_k(const float* __restrict__ partials,
                              float* __restrict__ stats)
{
    int bg = threadIdx.x;
    float s = 0, q = 0;
    for (int c = 0; c < 8; c++) {
        s += partials[(bg*8 + c)*2 + 0];
        q += partials[(bg*8 + c)*2 + 1];
    }
    float mean = s * (1.f/393216.f);
    float var  = q * (1.f/393216.f) - mean*mean;
    stats[bg*2 + 0] = mean;
    stats[bg*2 + 1] = rsqrtf(var + 1e-5f);
}

// ---------------- time-embedding MLP (96 blocks) -----------------------------
__global__ void temb_k(const float* __restrict__ te, const float* __restrict__ wt,
                       const float* __restrict__ bt, float* __restrict__ film)
{
    __shared__ float sh[256];
    int b = blockIdx.x, j = blockIdx.y*32 + threadIdx.x;
    for (int i = threadIdx.x; i < 256; i += 32) sh[i] = te[b*256 + i];
    __syncthreads();
    const float* wr = wt + j*256;
    float s = bt[j];
#pragma unroll 4
    for (int k = 0; k < 256; k++) s += sh[k]*wr[k];
    s = s / (1.f + expf(-s));
    film[b*192 + j] = s;
}

// ---------------- apply GN1 + SiLU + FiLM ------------------------------------
__global__ __launch_bounds__(256) void apply1_k(
    const float* __restrict__ x, const float* __restrict__ stats,
    const float* __restrict__ g1, const float* __restrict__ be1,
    const float* __restrict__ film, float* __restrict__ out)
{
    int idx4 = blockIdx.x*256 + threadIdx.x;
    if (idx4 >= NPIX/4) return;
    int flat = idx4 << 2;
    int cimg = flat >> 14;
    int b = cimg / 96, c = cimg - 96*b;
    int bg = b*4 + c/24;
    float mean = stats[bg*2], rstd = stats[bg*2+1];
    float gam = g1[c]*rstd;
    float bet = be1[c] - mean*gam;
    float shf = 1.f + film[b*192 + c];
    float bia = film[b*192 + 96 + c];
    float4 v = *(const float4*)&x[flat];
    float t;
    t = v.x*gam + bet; t = t/(1.f+expf(-t)); v.x = t*shf + bia;
    t = v.y*gam + bet; t = t/(1.f+expf(-t)); v.y = t*shf + bia;
    t = v.z*gam + bet; t = t/(1.f+expf(-t)); v.z = t*shf + bia;
    t = v.w*gam + bet; t = t/(1.f+expf(-t)); v.w = t*shf + bia;
    *(float4*)&out[flat] = v;
}

// ---------------- final: SiLU(GN(conv2)) -> d_out ----------------------------
__global__ __launch_bounds__(256) void apply3_k(
    const float* __restrict__ x, const float* __restrict__ stats,
    const float* __restrict__ g2, const float* __restrict__ be2,
    float* __restrict__ out)
{
    int idx4 = blockIdx.x*256 + threadIdx.x;
    if (idx4 >= NPIX/4) return;
    int flat = idx4 << 2;
    int cimg = flat >> 14;
    int b = cimg / 96, c = cimg - 96*b;
    int bg = b*4 + c/24;
    float mean = stats[bg*2], rstd = stats[bg*2+1];
    float gam = g2[c]*rstd;
    float bet = be2[c] - mean*gam;
    float4 v = *(const float4*)&x[flat];
    float t;
    t = v.x*gam + bet; v.x = t/(1.f+expf(-t));
    t = v.y*gam + bet; v.y = t/(1.f+expf(-t));
    t = v.z*gam + bet; v.z = t/(1.f+expf(-t));
    t = v.w*gam + bet; v.w = t/(1.f+expf(-t));
    *(float4*)&out[flat] = v;
}

// ---------------- attention core ---------------------------------------------
__global__ __launch_bounds__(256) void attn_core_k(
    const float* __restrict__ qkv, float* __restrict__ o0, float* __restrict__ o1)
{
    extern __shared__ float sm[];
    float* sq   = sm;
    float* slog = sq + 18432;
    float* spr  = slog + 576;

    int b = blockIdx.y, branch = blockIdx.z;
    int hn = blockIdx.x >> 4, wn = blockIdx.x & 15;
    int sh = branch*4;
    int h0 = hn*8 + sh, w0 = wn*8 + sh;
    int tid = threadIdx.x;

    for (int i = tid; i < 4608; i += 256) {
        int c = i >> 4, lq = i & 15, l = lq << 2;
        int gh = (h0 + (l >> 3)) & 127, gw = (w0 + (l & 7)) & 127;
        *(float4*)&sq[(c << 6) + l] =
            *(const float4*)&qkv[(((size_t)(b*288 + c)) << 14) + (gh << 7) + gw];
    }
    __syncthreads();

    const float scale = 0.40824829046386307f;
    for (int i = tid; i < 576; i += 256) {
        int head = i / 36, r = i - head*36, d = r / 6, e = r - d*6;
        const float* qp = &sq[(head*6 + d) << 6];
        const float* kp = &sq[(96 + head*6 + e) << 6];
        float a = 0.f;
#pragma unroll 8
        for (int l = 0; l < 64; l++) a += qp[l]*kp[l];
        slog[i] = a*scale;
    }
    __syncthreads();

    if (tid < 96) {
        int head = tid / 6, d = tid - head*6, base = head*36 + d*6;
        float m = -1e30f;
#pragma unroll
        for (int e = 0; e < 6; e++) m = fmaxf(m, slog[base+e]);
        float ex[6]; float s = 0.f;
#pragma unroll
        for (int e = 0; e < 6; e++) { ex[e] = expf(slog[base+e] - m); s += ex[e]; }
        float inv = 1.f/s;
#pragma unroll
        for (int e = 0; e < 6; e++) spr[base+e] = ex[e]*inv;
    }
    __syncthreads();

    float* o = branch ? o1 : o0;
    for (int i = tid; i < 1536; i += 256) {
        int ch = i >> 4, lq = i & 15, l = lq << 2;
        int head = ch / 6, d = ch - head*6;
        float4 a = {0.f, 0.f, 0.f, 0.f};
#pragma unroll
        for (int e = 0; e < 6; e++) {
            float p = spr[head*36 + d*6 + e];
            float4 vv = *(const float4*)&sq[((192 + head*6 + e) << 6) + l];
            a.x += p*vv.x; a.y += p*vv.y; a.z += p*vv.z; a.w += p*vv.w;
        }
        int gh = (h0 + (l >> 3)) & 127, gw = (w0 + (l & 7)) & 127;
        *(float4*)&o[(((size_t)(b*96 + ch)) << 14) + (gh << 7) + gw] = a;
    }
}

// ---------------- launch -----------------------------------------------------
extern "C" void kernel_launch(void* const* d_in, const int* in_sizes, int n_in,
                              void* d_out, int out_size)
{
    const float* x      = (const float*)d_in[0];
    const float* t_emb  = (const float*)d_in[1];
    const float* w1     = (const float*)d_in[2];
    const float* b1     = (const float*)d_in[3];
    const float* g1     = (const float*)d_in[4];
    const float* be1    = (const float*)d_in[5];
    const float* wt     = (const float*)d_in[6];
    const float* bt     = (const float*)d_in[7];
    const float* qkv_w  = (const float*)d_in[8];
    const float* qkv_b  = (const float*)d_in[9];
    const float* proj_w = (const float*)d_in[10];
    const float* proj_b = (const float*)d_in[11];
    const float* ga     = (const float*)d_in[12];
    const float* ba     = (const float*)d_in[13];
    const float* w2     = (const float*)d_in[14];
    const float* b2     = (const float*)d_in[15];
    const float* g2     = (const float*)d_in[16];
    const float* be2    = (const float*)d_in[17];
    float* out = (float*)d_out;

    float *buf1, *buf2, *buf3, *buf4, *qkvb, *partials, *stats, *film;
    uint32_t *w1hi, *w1lo, *w2hi, *w2lo, *qwhi, *qwlo, *pwhi, *pwlo;
    cudaGetSymbolAddress((void**)&buf1, g_buf1);
    cudaGetSymbolAddress((void**)&buf2, g_buf2);
    cudaGetSymbolAddress((void**)&buf3, g_buf3);
    cudaGetSymbolAddress((void**)&buf4, g_buf4);
    cudaGetSymbolAddress((void**)&qkvb, g_qkv);
    cudaGetSymbolAddress((void**)&partials, g_partials);
    cudaGetSymbolAddress((void**)&stats, g_stats);
    cudaGetSymbolAddress((void**)&film, g_film);
    cudaGetSymbolAddress((void**)&w1hi, g_w1hi);
    cudaGetSymbolAddress((void**)&w1lo, g_w1lo);
    cudaGetSymbolAddress((void**)&w2hi, g_w2hi);
    cudaGetSymbolAddress((void**)&w2lo, g_w2lo);
    cudaGetSymbolAddress((void**)&qwhi, g_qwhi);
    cudaGetSymbolAddress((void**)&qwlo, g_qwlo);
    cudaGetSymbolAddress((void**)&pwhi, g_pwhi);
    cudaGetSymbolAddress((void**)&pwlo, g_pwlo);

    const int ATTN_SMEM = (18432 + 576 + 576) * 4;
    cudaFuncSetAttribute(attn_core_k, cudaFuncAttributeMaxDynamicSharedMemorySize,
                         ATTN_SMEM);
    cudaFuncSetAttribute(conv3x3_mma_k, cudaFuncAttributeMaxDynamicSharedMemorySize,
                         CONV_SMEM);
    cudaFuncSetAttribute(qkv_mma_k, cudaFuncAttributeMaxDynamicSharedMemorySize,
                         CONV_SMEM);
    cudaFuncSetAttribute(proj_mma_k, cudaFuncAttributeMaxDynamicSharedMemorySize,
                         CONV_SMEM);

    dim3 cgrid(128, 16);
    dim3 rgrid(64, 8);

    // weight prepack (all four tensors)
    prep_k<<<dim3(162, 4), 256>>>(w1, w2, qkv_w, proj_w);
    // conv1
    conv3x3_mma_k<<<cgrid, 256, CONV_SMEM>>>(x, w1hi, w1lo, b1, buf1);
    // GN1 stats
    gn_reduce_k<<<rgrid, 256>>>(buf1, partials + 0*64*8*2);
    gn_finalize_k<<<1, 64>>>(partials + 0*64*8*2, stats + 0*64*2);
    // FiLM
    temb_k<<<dim3(16, 6), 32>>>(t_emb, wt, bt, film);
    // R
    apply1_k<<<NPIX/4/256, 256>>>(buf1, stats + 0*64*2, g1, be1, film, buf2);
    // GN2 stats
    gn_reduce_k<<<rgrid, 256>>>(buf2, partials + 1*64*8*2);
    gn_finalize_k<<<1, 64>>>(partials + 1*64*8*2, stats + 1*64*2);
    // qkv (GN2 fused, mma)
    qkv_mma_k<<<dim3(128, 3, 16), 256, CONV_SMEM>>>(buf2, stats + 1*64*2, ga, ba,
                                                    qwhi, qwlo, qkv_b, qkvb);
    // attention cores, both branches
    attn_core_k<<<dim3(256, 16, 2), 256, ATTN_SMEM>>>(qkvb, buf1, buf4);
    // proj + residual (mma)
    proj_mma_k<<<cgrid, 256, CONV_SMEM>>>(buf1, buf4, buf2, pwhi, pwlo,
                                          proj_b, buf3);
    // conv2
    conv3x3_mma_k<<<cgrid, 256, CONV_SMEM>>>(buf3, w2hi, w2lo, b2, buf1);
    // GN3 stats
    gn_reduce_k<<<rgrid, 256>>>(buf1, partials + 2*64*8*2);
    gn_finalize_k<<<1, 64>>>(partials + 2*64*8*2, stats + 2*64*2);
    // output
    apply3_k<<<NPIX/4/256, 256>>>(buf1, stats + 2*64*2, g2, be2, out);
}